// round 4
// baseline (speedup 1.0000x reference)
#include <cuda_runtime.h>
#include <math.h>

#define NMAX 100000
#define EMAX 600000
#define HMAX 128

// Scratch (static __device__ arrays — allocation-free per harness rules)
__device__ float g_bufA[(size_t)NMAX * HMAX];
__device__ float g_bufB[(size_t)NMAX * HMAX];
__device__ float g_deg[NMAX];
__device__ float g_dinv[NMAX];
__device__ float g_norm[EMAX];

// ---------------------------------------------------------------------------
// Degree / normalization precompute
// ---------------------------------------------------------------------------
__global__ void zero_deg_kernel(float* deg, int n) {
    int i = blockIdx.x * blockDim.x + threadIdx.x;
    if (i < n) deg[i] = 0.0f;
}

__global__ void count_deg_kernel(const int* __restrict__ col, float* deg, int E) {
    int e = blockIdx.x * blockDim.x + threadIdx.x;
    if (e < E) atomicAdd(&deg[col[e]], 1.0f);
}

__global__ void dinv_kernel(const float* __restrict__ deg, float* dinv, int n) {
    int i = blockIdx.x * blockDim.x + threadIdx.x;
    if (i < n) dinv[i] = rsqrtf(deg[i] + 1.0f);  // +1 self loop
}

__global__ void norm_kernel(const int* __restrict__ row, const int* __restrict__ col,
                            const float* __restrict__ dinv, float* __restrict__ norm, int E) {
    int e = blockIdx.x * blockDim.x + threadIdx.x;
    if (e < E) norm[e] = dinv[row[e]] * dinv[col[e]];
}

// ---------------------------------------------------------------------------
// Aggregation: out = S * h  (+ bias), where S has self loops with weight dinv^2
// Split into: init (self-loop + bias) then edge scatter (atomics).
// ---------------------------------------------------------------------------
template <int D, bool BIAS>
__global__ void agg_init_kernel(const float* __restrict__ h, const float* __restrict__ dinv,
                                const float* __restrict__ bias, float* __restrict__ out, int n) {
    int idx = blockIdx.x * blockDim.x + threadIdx.x;
    if (idx >= n * D) return;
    int i = idx / D;
    int f = idx - i * D;
    float di = dinv[i];
    float v = di * di * h[idx];
    if (BIAS) v += bias[f];
    out[idx] = v;
}

template <int D>
__global__ void agg_scatter_kernel(const float* __restrict__ h, const int* __restrict__ row,
                                   const int* __restrict__ col, const float* __restrict__ norm,
                                   float* __restrict__ out, int E) {
    constexpr int TPE = (D >= 4) ? (D / 4) : 1;  // threads per edge (float4 lanes)
    int gid = blockIdx.x * blockDim.x + threadIdx.x;
    int e = gid / TPE;
    int lane = gid - e * TPE;
    if (e >= E) return;
    int r = row[e];
    int c = col[e];
    float nv = norm[e];
    if (D >= 4) {
        float4 v = *reinterpret_cast<const float4*>(h + (size_t)r * D + lane * 4);
        float* dst = out + (size_t)c * D + lane * 4;
        atomicAdd(dst + 0, nv * v.x);
        atomicAdd(dst + 1, nv * v.y);
        atomicAdd(dst + 2, nv * v.z);
        atomicAdd(dst + 3, nv * v.w);
    } else if (D == 3) {
        const float* src = h + (size_t)r * 3;
        float* dst = out + (size_t)c * 3;
        atomicAdd(dst + 0, nv * src[0]);
        atomicAdd(dst + 1, nv * src[1]);
        atomicAdd(dst + 2, nv * src[2]);
    } else {  // D == 1
        atomicAdd(out + c, nv * h[r]);
    }
}

// ---------------------------------------------------------------------------
// Dense GEMM: C[N,M] = act_in(A[N,K]) @ W[K,M] (+bias) (optional relu out)
// 64x64 block tile, BK=16, 4x4 register tile, 256 threads.
// ---------------------------------------------------------------------------
template <bool ACT_IN, bool BIAS, bool ACT_OUT>
__global__ void gemm_kernel(const float* __restrict__ A, const float* __restrict__ W,
                            const float* __restrict__ bias, float* __restrict__ C,
                            int N, int K, int M) {
    constexpr int BM = 64, BN = 64, BK = 16, TM = 4, TN = 4;
    __shared__ float As[BK][BM];
    __shared__ float Bs[BK][BN];

    int tx = threadIdx.x % 16;
    int ty = threadIdx.x / 16;
    int row0 = blockIdx.y * BM;
    int col0 = blockIdx.x * BN;

    float acc[TM][TN] = {};

    for (int k0 = 0; k0 < K; k0 += BK) {
        // Load A tile (transposed into smem for conflict-free compute reads)
        for (int i = threadIdx.x; i < BM * BK; i += 256) {
            int r = i / BK, c = i % BK;
            int gr = row0 + r, gc = k0 + c;
            float v = (gr < N && gc < K) ? A[(size_t)gr * K + gc] : 0.0f;
            if (ACT_IN) v = fmaxf(v, 0.0f);
            As[c][r] = v;
        }
        // Load W tile
        for (int i = threadIdx.x; i < BK * BN; i += 256) {
            int r = i / BN, c = i % BN;
            int gr = k0 + r, gc = col0 + c;
            Bs[r][c] = (gr < K && gc < M) ? W[(size_t)gr * M + gc] : 0.0f;
        }
        __syncthreads();

#pragma unroll
        for (int kk = 0; kk < BK; kk++) {
            float a[TM], b[TN];
#pragma unroll
            for (int i = 0; i < TM; i++) a[i] = As[kk][ty * TM + i];
#pragma unroll
            for (int j = 0; j < TN; j++) b[j] = Bs[kk][tx * TN + j];
#pragma unroll
            for (int i = 0; i < TM; i++)
#pragma unroll
                for (int j = 0; j < TN; j++) acc[i][j] += a[i] * b[j];
        }
        __syncthreads();
    }

#pragma unroll
    for (int i = 0; i < TM; i++) {
        int gr = row0 + ty * TM + i;
        if (gr >= N) continue;
#pragma unroll
        for (int j = 0; j < TN; j++) {
            int gc = col0 + tx * TN + j;
            if (gc >= M) continue;
            float v = acc[i][j];
            if (BIAS) v += bias[gc];
            if (ACT_OUT) v = fmaxf(v, 0.0f);
            C[(size_t)gr * M + gc] = v;
        }
    }
}

// M=1 GEMV (layer 5): warp per row, shuffle reduce.
template <bool ACT_IN>
__global__ void gemv_kernel(const float* __restrict__ A, const float* __restrict__ w,
                            float* __restrict__ out, int N, int K) {
    int warp = (blockIdx.x * blockDim.x + threadIdx.x) / 32;
    int lane = threadIdx.x % 32;
    if (warp >= N) return;
    float acc = 0.0f;
    for (int k = lane; k < K; k += 32) {
        float v = A[(size_t)warp * K + k];
        if (ACT_IN) v = fmaxf(v, 0.0f);
        acc += v * w[k];
    }
#pragma unroll
    for (int off = 16; off > 0; off >>= 1) acc += __shfl_down_sync(0xffffffffu, acc, off);
    if (lane == 0) out[warp] = acc;
}

// ---------------------------------------------------------------------------
// Launch
// ---------------------------------------------------------------------------
extern "C" void kernel_launch(void* const* d_in, const int* in_sizes, int n_in,
                              void* d_out, int out_size) {
    const float* x  = (const float*)d_in[0];
    const int*   ei = (const int*)d_in[1];
    const float* W1 = (const float*)d_in[2];
    const float* b1 = (const float*)d_in[3];
    const float* W2 = (const float*)d_in[4];
    const float* b2 = (const float*)d_in[5];
    const float* W3 = (const float*)d_in[6];
    const float* b3 = (const float*)d_in[7];
    const float* W4 = (const float*)d_in[8];
    const float* b4 = (const float*)d_in[9];
    const float* W5 = (const float*)d_in[10];
    const float* b5 = (const float*)d_in[11];

    int N = in_sizes[0] / 3;
    int E = in_sizes[1] / 2;
    const int* row = ei;       // sources (gather index)
    const int* col = ei + E;   // targets (scatter index)

    float *bufA, *bufB, *deg, *dinv, *norm;
    cudaGetSymbolAddress((void**)&bufA, g_bufA);
    cudaGetSymbolAddress((void**)&bufB, g_bufB);
    cudaGetSymbolAddress((void**)&deg,  g_deg);
    cudaGetSymbolAddress((void**)&dinv, g_dinv);
    cudaGetSymbolAddress((void**)&norm, g_norm);

    const int T = 256;
    auto cdiv = [](long long a, long long b) { return (int)((a + b - 1) / b); };

    // Precompute normalization
    zero_deg_kernel<<<cdiv(N, T), T>>>(deg, N);
    count_deg_kernel<<<cdiv(E, T), T>>>(col, deg, E);
    dinv_kernel<<<cdiv(N, T), T>>>(deg, dinv, N);
    norm_kernel<<<cdiv(E, T), T>>>(row, col, dinv, norm, E);

    // L1: aggregate at D=3 first (S is linear: S(xW) = (Sx)W), then 3->128 GEMM.
    agg_init_kernel<3, false><<<cdiv((long long)N * 3, T), T>>>(x, dinv, nullptr, bufA, N);
    agg_scatter_kernel<3><<<cdiv(E, T), T>>>(x, row, col, norm, bufA, E);
    {
        dim3 g(2, cdiv(N, 64));
        gemm_kernel<false, true, true><<<g, T>>>(bufA, W1, b1, bufB, N, 3, 128);  // h1 (relu'd)
    }

    // L2: GEMM 128->128 then aggregate (+b2 in init); relu deferred into L3 GEMM load.
    {
        dim3 g(2, cdiv(N, 64));
        gemm_kernel<false, false, false><<<g, T>>>(bufB, W2, nullptr, bufA, N, 128, 128);
    }
    agg_init_kernel<128, true><<<cdiv((long long)N * 128, T), T>>>(bufA, dinv, b2, bufB, N);
    agg_scatter_kernel<128><<<cdiv((long long)E * 32, T), T>>>(bufA, row, col, norm, bufB, E);

    // L3: relu(a2) @ W3 (128->64), then aggregate at D=64 (+b3).
    {
        dim3 g(1, cdiv(N, 64));
        gemm_kernel<true, false, false><<<g, T>>>(bufB, W3, nullptr, bufA, N, 128, 64);
    }
    agg_init_kernel<64, true><<<cdiv((long long)N * 64, T), T>>>(bufA, dinv, b3, bufB, N);
    agg_scatter_kernel<64><<<cdiv((long long)E * 16, T), T>>>(bufA, row, col, norm, bufB, E);

    // L4: relu(a3) @ W4 (64->64), then aggregate (+b4).
    {
        dim3 g(1, cdiv(N, 64));
        gemm_kernel<true, false, false><<<g, T>>>(bufB, W4, nullptr, bufA, N, 64, 64);
    }
    agg_init_kernel<64, true><<<cdiv((long long)N * 64, T), T>>>(bufA, dinv, b4, bufB, N);
    agg_scatter_kernel<64><<<cdiv((long long)E * 16, T), T>>>(bufA, row, col, norm, bufB, E);

    // L5: relu(a4) @ W5 (64->1) via warp GEMV, then aggregate at D=1 (+b5) into d_out.
    gemv_kernel<true><<<cdiv((long long)N * 32, T), T>>>(bufB, W5, bufA, N, 64);
    float* out = (float*)d_out;
    agg_init_kernel<1, true><<<cdiv(N, T), T>>>(bufA, dinv, b5, out, N);
    agg_scatter_kernel<1><<<cdiv(E, T), T>>>(bufA, row, col, norm, out, E);
}

// round 5
// speedup vs baseline: 3.4772x; 3.4772x over previous
#include <cuda_runtime.h>
#include <math.h>

#define NMAX 100000
#define EMAX 600000
#define HMAX 128

// Scratch (static __device__ arrays — allocation-free per harness rules)
__device__ float g_bufA[(size_t)NMAX * HMAX];
__device__ float g_bufB[(size_t)NMAX * HMAX];
__device__ int   g_deg[NMAX];
__device__ int   g_cnt[NMAX];
__device__ int   g_rowptr[NMAX + 1];
__device__ int   g_blocksums[(NMAX + 1023) / 1024 + 1];
__device__ float g_dinv[NMAX];
__device__ int   g_csrc[EMAX];   // CSR source index per edge (grouped by target)
__device__ float g_cw[EMAX];     // CSR edge weight (norm)

// ---------------------------------------------------------------------------
// CSR build: degree -> exclusive scan -> fill (by target node)
// ---------------------------------------------------------------------------
__global__ void count_deg_kernel(const int* __restrict__ col, int* deg, int E) {
    int e = blockIdx.x * blockDim.x + threadIdx.x;
    if (e < E) atomicAdd(&deg[col[e]], 1);
}

__global__ void dinv_kernel(const int* __restrict__ deg, float* dinv, int n) {
    int i = blockIdx.x * blockDim.x + threadIdx.x;
    if (i < n) dinv[i] = rsqrtf((float)deg[i] + 1.0f);  // +1 self loop
}

__global__ void scan_block_kernel(const int* __restrict__ deg, int* excl,
                                  int* blocksums, int n) {
    __shared__ int sm[1024];
    int i = blockIdx.x * 1024 + threadIdx.x;
    int v = (i < n) ? deg[i] : 0;
    sm[threadIdx.x] = v;
    __syncthreads();
    for (int off = 1; off < 1024; off <<= 1) {
        int t = (threadIdx.x >= off) ? sm[threadIdx.x - off] : 0;
        __syncthreads();
        sm[threadIdx.x] += t;
        __syncthreads();
    }
    if (i < n) excl[i] = sm[threadIdx.x] - v;
    if (threadIdx.x == 1023) blocksums[blockIdx.x] = sm[1023];
}

__global__ void scan_sums_kernel(int* blocksums, int nb) {
    if (threadIdx.x == 0 && blockIdx.x == 0) {
        int run = 0;
        for (int b = 0; b < nb; b++) { int t = blocksums[b]; blocksums[b] = run; run += t; }
    }
}

__global__ void scan_add_kernel(int* rowptr, const int* __restrict__ blocksums, int n, int E) {
    int i = blockIdx.x * blockDim.x + threadIdx.x;
    if (i < n) rowptr[i] += blocksums[i >> 10];
    if (i == 0) rowptr[n] = E;
}

__global__ void csr_fill_kernel(const int* __restrict__ row, const int* __restrict__ col,
                                const float* __restrict__ dinv, const int* __restrict__ rowptr,
                                int* cnt, int* __restrict__ csrc, float* __restrict__ cw, int E) {
    int e = blockIdx.x * blockDim.x + threadIdx.x;
    if (e >= E) return;
    int r = row[e], c = col[e];
    int pos = rowptr[c] + atomicAdd(&cnt[c], 1);
    csrc[pos] = r;
    cw[pos] = dinv[r] * dinv[c];
}

// ---------------------------------------------------------------------------
// CSR aggregation: out[i] = dinv[i]^2*h[i] + sum_e w[e]*h[src[e]]  (+bias)(relu)
// D/4 float4 lanes per node; fully coalesced writes, no atomics.
// ---------------------------------------------------------------------------
template <int D, bool BIAS, bool RELU>
__global__ void agg_csr_kernel(const float* __restrict__ h, const int* __restrict__ rp,
                               const int* __restrict__ src, const float* __restrict__ w,
                               const float* __restrict__ dinv, const float* __restrict__ bias,
                               float* __restrict__ out, int N) {
    constexpr int TPN = D / 4;
    int tid = blockIdx.x * blockDim.x + threadIdx.x;
    int node = tid / TPN;
    int lane = tid - node * TPN;
    if (node >= N) return;
    int beg = rp[node], end = rp[node + 1];
    float di = dinv[node];
    float w0 = di * di;
    const float4* hv = reinterpret_cast<const float4*>(h);
    float4 s = hv[(size_t)node * TPN + lane];
    float4 acc = make_float4(w0 * s.x, w0 * s.y, w0 * s.z, w0 * s.w);
    for (int e = beg; e < end; e++) {
        int si = src[e];
        float ww = w[e];
        float4 v = hv[(size_t)si * TPN + lane];
        acc.x += ww * v.x; acc.y += ww * v.y; acc.z += ww * v.z; acc.w += ww * v.w;
    }
    if (BIAS) {
        float4 b = reinterpret_cast<const float4*>(bias)[lane];
        acc.x += b.x; acc.y += b.y; acc.z += b.z; acc.w += b.w;
    }
    if (RELU) {
        acc.x = fmaxf(acc.x, 0.f); acc.y = fmaxf(acc.y, 0.f);
        acc.z = fmaxf(acc.z, 0.f); acc.w = fmaxf(acc.w, 0.f);
    }
    reinterpret_cast<float4*>(out)[(size_t)node * TPN + lane] = acc;
}

// D=3 aggregation of raw input x (no bias / relu)
__global__ void agg_csr3_kernel(const float* __restrict__ x, const int* __restrict__ rp,
                                const int* __restrict__ src, const float* __restrict__ w,
                                const float* __restrict__ dinv, float* __restrict__ out, int N) {
    int i = blockIdx.x * blockDim.x + threadIdx.x;
    if (i >= N) return;
    float di = dinv[i];
    float w0 = di * di;
    float a0 = w0 * x[(size_t)i * 3 + 0];
    float a1 = w0 * x[(size_t)i * 3 + 1];
    float a2 = w0 * x[(size_t)i * 3 + 2];
    int beg = rp[i], end = rp[i + 1];
    for (int e = beg; e < end; e++) {
        int s = src[e];
        float ww = w[e];
        a0 += ww * x[(size_t)s * 3 + 0];
        a1 += ww * x[(size_t)s * 3 + 1];
        a2 += ww * x[(size_t)s * 3 + 2];
    }
    out[(size_t)i * 3 + 0] = a0;
    out[(size_t)i * 3 + 1] = a1;
    out[(size_t)i * 3 + 2] = a2;
}

// D=1 aggregation (+scalar bias) for the final layer
__global__ void agg_csr1_kernel(const float* __restrict__ h, const int* __restrict__ rp,
                                const int* __restrict__ src, const float* __restrict__ w,
                                const float* __restrict__ dinv, const float* __restrict__ bias,
                                float* __restrict__ out, int N) {
    int i = blockIdx.x * blockDim.x + threadIdx.x;
    if (i >= N) return;
    float di = dinv[i];
    float acc = di * di * h[i];
    int beg = rp[i], end = rp[i + 1];
    for (int e = beg; e < end; e++) acc += w[e] * h[src[e]];
    out[i] = acc + bias[0];
}

// ---------------------------------------------------------------------------
// Dense GEMM: C[N,M] = A[N,K] @ W[K,M] (+bias)(relu)
// BMxBN tile, BK=16, TMxTN register tile, 256 threads, float4 frag loads.
// TM=8 always; TN in {8, 4}. Split-half register blocking for broadcast/
// conflict-free smem frag loads.
// ---------------------------------------------------------------------------
template <int BM, int BN, int TN, bool BIAS, bool RELU>
__global__ __launch_bounds__(256) void gemm_kernel(
    const float* __restrict__ A, const float* __restrict__ W,
    const float* __restrict__ bias, float* __restrict__ C, int N, int K, int M) {
    constexpr int BK = 16;
    constexpr int TM = 8;
    constexpr int NCJ = TN / 4;  // 2 or 1 column chunks
    static_assert((BM / TM) * (BN / TN) == 256, "thread count");

    __shared__ float As[BK * BM];  // transposed: As[k][m]
    __shared__ float Bs[BK * BN];  // Bs[k][n]

    int tx = threadIdx.x % (BN / TN);   // 16
    int ty = threadIdx.x / (BN / TN);   // 16
    int row0 = blockIdx.y * BM;
    int col0 = blockIdx.x * BN;

    float acc[2][4][NCJ][4] = {};

    const bool kvec = (K % 4 == 0);

    for (int k0 = 0; k0 < K; k0 += BK) {
        // ---- load A tile (transposed into smem) ----
        if (kvec) {
            constexpr int QA = BM * BK / 4 / 256;  // float4 loads per thread
#pragma unroll
            for (int t = 0; t < QA; t++) {
                int i = threadIdx.x + t * 256;
                int r = i / (BK / 4);
                int kq = i - r * (BK / 4);
                int gr = row0 + r;
                float4 v = make_float4(0.f, 0.f, 0.f, 0.f);
                if (gr < N) v = *reinterpret_cast<const float4*>(A + (size_t)gr * K + k0 + kq * 4);
                As[(kq * 4 + 0) * BM + r] = v.x;
                As[(kq * 4 + 1) * BM + r] = v.y;
                As[(kq * 4 + 2) * BM + r] = v.z;
                As[(kq * 4 + 3) * BM + r] = v.w;
            }
        } else {
            for (int i = threadIdx.x; i < BM * BK; i += 256) {
                int r = i / BK, c = i - (i / BK) * BK;
                int gr = row0 + r, gc = k0 + c;
                As[c * BM + r] = (gr < N && gc < K) ? A[(size_t)gr * K + gc] : 0.0f;
            }
        }
        // ---- load W tile ----
        {
            constexpr int QB = BK * BN / 4 / 256;
#pragma unroll
            for (int t = 0; t < QB; t++) {
                int i = threadIdx.x + t * 256;
                int r = i / (BN / 4);
                int cq = i - r * (BN / 4);
                int gr = k0 + r;
                float4 v = make_float4(0.f, 0.f, 0.f, 0.f);
                if (gr < K) v = *reinterpret_cast<const float4*>(W + (size_t)gr * M + col0 + cq * 4);
                *reinterpret_cast<float4*>(&Bs[r * BN + cq * 4]) = v;
            }
        }
        __syncthreads();

#pragma unroll
        for (int kk = 0; kk < BK; kk++) {
            float4 a0 = *reinterpret_cast<const float4*>(&As[kk * BM + ty * 4]);
            float4 a1 = *reinterpret_cast<const float4*>(&As[kk * BM + BM / 2 + ty * 4]);
            float ar[2][4] = {{a0.x, a0.y, a0.z, a0.w}, {a1.x, a1.y, a1.z, a1.w}};
            float bc[NCJ][4];
            {
                float4 b0 = *reinterpret_cast<const float4*>(&Bs[kk * BN + tx * 4]);
                bc[0][0] = b0.x; bc[0][1] = b0.y; bc[0][2] = b0.z; bc[0][3] = b0.w;
                if (NCJ == 2) {
                    float4 b1 = *reinterpret_cast<const float4*>(&Bs[kk * BN + BN / 2 + tx * 4]);
                    bc[1][0] = b1.x; bc[1][1] = b1.y; bc[1][2] = b1.z; bc[1][3] = b1.w;
                }
            }
#pragma unroll
            for (int ri = 0; ri < 2; ri++)
#pragma unroll
                for (int i = 0; i < 4; i++)
#pragma unroll
                    for (int cj = 0; cj < NCJ; cj++)
#pragma unroll
                        for (int j = 0; j < 4; j++)
                            acc[ri][i][cj][j] += ar[ri][i] * bc[cj][j];
        }
        __syncthreads();
    }

    // ---- epilogue ----
#pragma unroll
    for (int ri = 0; ri < 2; ri++) {
#pragma unroll
        for (int i = 0; i < 4; i++) {
            int gr = row0 + ri * (BM / 2) + ty * 4 + i;
            if (gr >= N) continue;
#pragma unroll
            for (int cj = 0; cj < NCJ; cj++) {
                int gc = col0 + cj * (BN / 2) + tx * 4;
                float4 v = make_float4(acc[ri][i][cj][0], acc[ri][i][cj][1],
                                       acc[ri][i][cj][2], acc[ri][i][cj][3]);
                if (BIAS) {
                    float4 b = *reinterpret_cast<const float4*>(bias + gc);
                    v.x += b.x; v.y += b.y; v.z += b.z; v.w += b.w;
                }
                if (RELU) {
                    v.x = fmaxf(v.x, 0.f); v.y = fmaxf(v.y, 0.f);
                    v.z = fmaxf(v.z, 0.f); v.w = fmaxf(v.w, 0.f);
                }
                *reinterpret_cast<float4*>(C + (size_t)gr * M + gc) = v;
            }
        }
    }
}

// M=1 GEMV (layer 5): warp per row, shuffle reduce. Input already relu'd.
__global__ void gemv_kernel(const float* __restrict__ A, const float* __restrict__ w,
                            float* __restrict__ out, int N, int K) {
    int warp = (blockIdx.x * blockDim.x + threadIdx.x) / 32;
    int lane = threadIdx.x % 32;
    if (warp >= N) return;
    float acc = 0.0f;
    for (int k = lane; k < K; k += 32) acc += A[(size_t)warp * K + k] * w[k];
#pragma unroll
    for (int off = 16; off > 0; off >>= 1) acc += __shfl_down_sync(0xffffffffu, acc, off);
    if (lane == 0) out[warp] = acc;
}

// ---------------------------------------------------------------------------
// Launch
// ---------------------------------------------------------------------------
extern "C" void kernel_launch(void* const* d_in, const int* in_sizes, int n_in,
                              void* d_out, int out_size) {
    const float* x  = (const float*)d_in[0];
    const int*   ei = (const int*)d_in[1];
    const float* W1 = (const float*)d_in[2];
    const float* b1 = (const float*)d_in[3];
    const float* W2 = (const float*)d_in[4];
    const float* b2 = (const float*)d_in[5];
    const float* W3 = (const float*)d_in[6];
    const float* b3 = (const float*)d_in[7];
    const float* W4 = (const float*)d_in[8];
    const float* b4 = (const float*)d_in[9];
    const float* W5 = (const float*)d_in[10];
    const float* b5 = (const float*)d_in[11];

    int N = in_sizes[0] / 3;
    int E = in_sizes[1] / 2;
    const int* row = ei;       // sources (gather index)
    const int* col = ei + E;   // targets (aggregation index)

    float *bufA, *bufB, *dinv, *cw;
    int *deg, *cnt, *rowptr, *blocksums, *csrc;
    cudaGetSymbolAddress((void**)&bufA, g_bufA);
    cudaGetSymbolAddress((void**)&bufB, g_bufB);
    cudaGetSymbolAddress((void**)&deg, g_deg);
    cudaGetSymbolAddress((void**)&cnt, g_cnt);
    cudaGetSymbolAddress((void**)&rowptr, g_rowptr);
    cudaGetSymbolAddress((void**)&blocksums, g_blocksums);
    cudaGetSymbolAddress((void**)&dinv, g_dinv);
    cudaGetSymbolAddress((void**)&csrc, g_csrc);
    cudaGetSymbolAddress((void**)&cw, g_cw);

    const int T = 256;
    auto cdiv = [](long long a, long long b) { return (int)((a + b - 1) / b); };
    int nb = cdiv(N, 1024);

    // ---- CSR build ----
    cudaMemsetAsync(deg, 0, (size_t)N * sizeof(int));
    cudaMemsetAsync(cnt, 0, (size_t)N * sizeof(int));
    count_deg_kernel<<<cdiv(E, T), T>>>(col, deg, E);
    dinv_kernel<<<cdiv(N, T), T>>>(deg, dinv, N);
    scan_block_kernel<<<nb, 1024>>>(deg, rowptr, blocksums, N);
    scan_sums_kernel<<<1, 32>>>(blocksums, nb);
    scan_add_kernel<<<cdiv(N, T), T>>>(rowptr, blocksums, N, E);
    csr_fill_kernel<<<cdiv(E, T), T>>>(row, col, dinv, rowptr, cnt, csrc, cw, E);

    // ---- L1: agg(x) [D=3], then GEMM 3->128 (+b1, relu) ----
    agg_csr3_kernel<<<cdiv(N, T), T>>>(x, rowptr, csrc, cw, dinv, bufA, N);
    {
        dim3 g(1, cdiv(N, 128));
        gemm_kernel<128, 128, 8, true, true><<<g, T>>>(bufA, W1, b1, bufB, N, 3, 128);
    }

    // ---- L2: GEMM 128->128, then agg (+b2, relu) ----
    {
        dim3 g(1, cdiv(N, 128));
        gemm_kernel<128, 128, 8, false, false><<<g, T>>>(bufB, W2, nullptr, bufA, N, 128, 128);
    }
    agg_csr_kernel<128, true, true><<<cdiv((long long)N * 32, T), T>>>(
        bufA, rowptr, csrc, cw, dinv, b2, bufB, N);

    // ---- L3: GEMM 128->64, then agg (+b3, relu) ----
    {
        dim3 g(1, cdiv(N, 128));
        gemm_kernel<128, 64, 4, false, false><<<g, T>>>(bufB, W3, nullptr, bufA, N, 128, 64);
    }
    agg_csr_kernel<64, true, true><<<cdiv((long long)N * 16, T), T>>>(
        bufA, rowptr, csrc, cw, dinv, b3, bufB, N);

    // ---- L4: GEMM 64->64, then agg (+b4, relu) ----
    {
        dim3 g(1, cdiv(N, 128));
        gemm_kernel<128, 64, 4, false, false><<<g, T>>>(bufB, W4, nullptr, bufA, N, 64, 64);
    }
    agg_csr_kernel<64, true, true><<<cdiv((long long)N * 16, T), T>>>(
        bufA, rowptr, csrc, cw, dinv, b4, bufB, N);

    // ---- L5: GEMV 64->1, then agg (+b5) into d_out ----
    gemv_kernel<<<cdiv((long long)N * 32, T), T>>>(bufB, W5, bufA, N, 64);
    agg_csr1_kernel<<<cdiv(N, T), T>>>(bufA, rowptr, csrc, cw, dinv, b5, (float*)d_out, N);
}

// round 10
// speedup vs baseline: 4.4073x; 1.2675x over previous
#include <cuda_runtime.h>
#include <math.h>
#include <stdint.h>

#define NMAX 100000
#define EMAX 600000
#define HMAX 128

// Scratch (static __device__ arrays — allocation-free per harness rules)
__device__ float g_bufA[(size_t)NMAX * HMAX];
__device__ float g_bufB[(size_t)NMAX * HMAX];
__device__ int   g_deg[NMAX];
__device__ int   g_cnt[NMAX];
__device__ int   g_rowptr[NMAX + 1];
__device__ int   g_blocksums[(NMAX + 1023) / 1024 + 1];
__device__ float g_dinv[NMAX];
__device__ int   g_csrc[EMAX];   // CSR source index per edge (grouped by target)
__device__ float g_cw[EMAX];     // CSR edge weight (norm)

// ---------------------------------------------------------------------------
// CSR build: degree -> exclusive scan -> fill (by target node)
// ---------------------------------------------------------------------------
__global__ void count_deg_kernel(const int* __restrict__ col, int* deg, int E) {
    int e = blockIdx.x * blockDim.x + threadIdx.x;
    if (e < E) atomicAdd(&deg[col[e]], 1);
}

__global__ void dinv_kernel(const int* __restrict__ deg, float* dinv, int n) {
    int i = blockIdx.x * blockDim.x + threadIdx.x;
    if (i < n) dinv[i] = rsqrtf((float)deg[i] + 1.0f);  // +1 self loop
}

__global__ void scan_block_kernel(const int* __restrict__ deg, int* excl,
                                  int* blocksums, int n) {
    __shared__ int sm[1024];
    int i = blockIdx.x * 1024 + threadIdx.x;
    int v = (i < n) ? deg[i] : 0;
    sm[threadIdx.x] = v;
    __syncthreads();
    for (int off = 1; off < 1024; off <<= 1) {
        int t = (threadIdx.x >= off) ? sm[threadIdx.x - off] : 0;
        __syncthreads();
        sm[threadIdx.x] += t;
        __syncthreads();
    }
    if (i < n) excl[i] = sm[threadIdx.x] - v;
    if (threadIdx.x == 1023) blocksums[blockIdx.x] = sm[1023];
}

// Parallel exclusive scan of per-block sums (nb <= 128)
__global__ void scan_sums_kernel(int* bs, int nb) {
    __shared__ int sm[128];
    int v = (threadIdx.x < nb) ? bs[threadIdx.x] : 0;
    sm[threadIdx.x] = v;
    __syncthreads();
    for (int off = 1; off < 128; off <<= 1) {
        int t = (threadIdx.x >= off) ? sm[threadIdx.x - off] : 0;
        __syncthreads();
        sm[threadIdx.x] += t;
        __syncthreads();
    }
    if (threadIdx.x < nb) bs[threadIdx.x] = sm[threadIdx.x] - v;
}

__global__ void scan_add_kernel(int* rowptr, const int* __restrict__ blocksums, int n, int E) {
    int i = blockIdx.x * blockDim.x + threadIdx.x;
    if (i < n) rowptr[i] += blocksums[i >> 10];
    if (i == 0) rowptr[n] = E;
}

__global__ void csr_fill_kernel(const int* __restrict__ row, const int* __restrict__ col,
                                const float* __restrict__ dinv, const int* __restrict__ rowptr,
                                int* cnt, int* __restrict__ csrc, float* __restrict__ cw, int E) {
    int e = blockIdx.x * blockDim.x + threadIdx.x;
    if (e >= E) return;
    int r = row[e], c = col[e];
    int pos = rowptr[c] + atomicAdd(&cnt[c], 1);
    csrc[pos] = r;
    cw[pos] = dinv[r] * dinv[c];
}

// ---------------------------------------------------------------------------
// CSR aggregation: out[i] = dinv[i]^2*h[i] + sum_e w[e]*h[src[e]]  (+bias)(relu)
// ---------------------------------------------------------------------------
template <int D, bool BIAS, bool RELU>
__global__ void agg_csr_kernel(const float* __restrict__ h, const int* __restrict__ rp,
                               const int* __restrict__ src, const float* __restrict__ w,
                               const float* __restrict__ dinv, const float* __restrict__ bias,
                               float* __restrict__ out, int N) {
    constexpr int TPN = D / 4;
    int tid = blockIdx.x * blockDim.x + threadIdx.x;
    int node = tid / TPN;
    int lane = tid - node * TPN;
    if (node >= N) return;
    int beg = rp[node], end = rp[node + 1];
    float di = dinv[node];
    float w0 = di * di;
    const float4* hv = reinterpret_cast<const float4*>(h);
    float4 s = hv[(size_t)node * TPN + lane];
    float4 acc = make_float4(w0 * s.x, w0 * s.y, w0 * s.z, w0 * s.w);
    for (int e = beg; e < end; e++) {
        int si = src[e];
        float ww = w[e];
        float4 v = hv[(size_t)si * TPN + lane];
        acc.x += ww * v.x; acc.y += ww * v.y; acc.z += ww * v.z; acc.w += ww * v.w;
    }
    if (BIAS) {
        float4 b = reinterpret_cast<const float4*>(bias)[lane];
        acc.x += b.x; acc.y += b.y; acc.z += b.z; acc.w += b.w;
    }
    if (RELU) {
        acc.x = fmaxf(acc.x, 0.f); acc.y = fmaxf(acc.y, 0.f);
        acc.z = fmaxf(acc.z, 0.f); acc.w = fmaxf(acc.w, 0.f);
    }
    reinterpret_cast<float4*>(out)[(size_t)node * TPN + lane] = acc;
}

// D=3 aggregation of raw input x (no bias / relu)
__global__ void agg_csr3_kernel(const float* __restrict__ x, const int* __restrict__ rp,
                                const int* __restrict__ src, const float* __restrict__ w,
                                const float* __restrict__ dinv, float* __restrict__ out, int N) {
    int i = blockIdx.x * blockDim.x + threadIdx.x;
    if (i >= N) return;
    float di = dinv[i];
    float w0 = di * di;
    float a0 = w0 * x[(size_t)i * 3 + 0];
    float a1 = w0 * x[(size_t)i * 3 + 1];
    float a2 = w0 * x[(size_t)i * 3 + 2];
    int beg = rp[i], end = rp[i + 1];
    for (int e = beg; e < end; e++) {
        int s = src[e];
        float ww = w[e];
        a0 += ww * x[(size_t)s * 3 + 0];
        a1 += ww * x[(size_t)s * 3 + 1];
        a2 += ww * x[(size_t)s * 3 + 2];
    }
    out[(size_t)i * 3 + 0] = a0;
    out[(size_t)i * 3 + 1] = a1;
    out[(size_t)i * 3 + 2] = a2;
}

// D=1 aggregation (+scalar bias) for the final layer
__global__ void agg_csr1_kernel(const float* __restrict__ h, const int* __restrict__ rp,
                                const int* __restrict__ src, const float* __restrict__ w,
                                const float* __restrict__ dinv, const float* __restrict__ bias,
                                float* __restrict__ out, int N) {
    int i = blockIdx.x * blockDim.x + threadIdx.x;
    if (i >= N) return;
    float di = dinv[i];
    float acc = di * di * h[i];
    int beg = rp[i], end = rp[i + 1];
    for (int e = beg; e < end; e++) acc += w[e] * h[src[e]];
    out[i] = acc + bias[0];
}

// ---------------------------------------------------------------------------
// TF32 tensor-core GEMM: C[N,M] = A[N,K] @ W[K,M]   (raw output; bias/relu
// are fused into the following aggregation pass)
// BM=128, BK=32, 256 threads (8 warps), mma.sync.m16n8k8.tf32.
// BN=128: warps 2x4 (warp tile 64x32); BN=64: warps 4x2 (warp tile 32x32).
// Requires K % 32 == 0 and M % BN == 0 handled by grid.
// ---------------------------------------------------------------------------
__device__ __forceinline__ uint32_t f2tf32(float f) {
    uint32_t r;
    asm("cvt.rna.tf32.f32 %0, %1;" : "=r"(r) : "f"(f));
    return r;
}

__device__ __forceinline__ void mma_tf32(float* d, const uint32_t* a, const uint32_t* b) {
    asm volatile(
        "mma.sync.aligned.m16n8k8.row.col.f32.tf32.tf32.f32 "
        "{%0,%1,%2,%3},{%4,%5,%6,%7},{%8,%9},{%0,%1,%2,%3};"
        : "+f"(d[0]), "+f"(d[1]), "+f"(d[2]), "+f"(d[3])
        : "r"(a[0]), "r"(a[1]), "r"(a[2]), "r"(a[3]), "r"(b[0]), "r"(b[1]));
}

template <int BN, int MW, int NW>
__global__ __launch_bounds__(256) void gemm_tf32_kernel(
    const float* __restrict__ A, const float* __restrict__ W,
    float* __restrict__ C, int N, int K, int M) {
    constexpr int BM = 128, BK = 32;
    constexpr int WMT = BM / MW;       // warp tile M
    constexpr int WNT = BN / NW;       // warp tile N
    constexpr int MF = WMT / 16, NF = WNT / 8;
    constexpr int LDS = BK + 4;        // padded row (words)

    __shared__ uint32_t As[BM * LDS];  // As[m][k], tf32
    __shared__ uint32_t Bs[BN * LDS];  // Bs[n][k] = W[k][n], tf32

    int tid = threadIdx.x;
    int wid = tid >> 5, lane = tid & 31;
    int wm = wid / NW, wn = wid % NW;
    int row0 = blockIdx.y * BM, col0 = blockIdx.x * BN;

    float acc[MF][NF][4] = {};

    for (int k0 = 0; k0 < K; k0 += BK) {
        // ---- A tile: BM x BK, float4 along k ----
#pragma unroll
        for (int t = 0; t < 4; t++) {
            int i = tid + t * 256;         // 0..1023
            int r = i >> 3;
            int kq = i & 7;
            int gr = row0 + r;
            float4 v = make_float4(0.f, 0.f, 0.f, 0.f);
            if (gr < N) v = *reinterpret_cast<const float4*>(A + (size_t)gr * K + k0 + kq * 4);
            uint32_t* dst = &As[r * LDS + kq * 4];
            dst[0] = f2tf32(v.x); dst[1] = f2tf32(v.y);
            dst[2] = f2tf32(v.z); dst[3] = f2tf32(v.w);
        }
        // ---- W tile: BK x BN, transpose into Bs[n][k] ----
        constexpr int QB = BK * BN / 4 / 256;
#pragma unroll
        for (int t = 0; t < QB; t++) {
            int i = tid + t * 256;
            int r = i / (BN / 4);          // k in [0,32)
            int cq = i % (BN / 4);
            float4 v = *reinterpret_cast<const float4*>(W + (size_t)(k0 + r) * M + col0 + cq * 4);
            Bs[(cq * 4 + 0) * LDS + r] = f2tf32(v.x);
            Bs[(cq * 4 + 1) * LDS + r] = f2tf32(v.y);
            Bs[(cq * 4 + 2) * LDS + r] = f2tf32(v.z);
            Bs[(cq * 4 + 3) * LDS + r] = f2tf32(v.w);
        }
        __syncthreads();

#pragma unroll
        for (int kk = 0; kk < BK; kk += 8) {
            uint32_t af[MF][4], bf[NF][2];
            int c = kk + (lane & 3);
            int rq = lane >> 2;
#pragma unroll
            for (int mi = 0; mi < MF; mi++) {
                int r = wm * WMT + mi * 16 + rq;
                af[mi][0] = As[r * LDS + c];
                af[mi][1] = As[(r + 8) * LDS + c];
                af[mi][2] = As[r * LDS + c + 4];
                af[mi][3] = As[(r + 8) * LDS + c + 4];
            }
#pragma unroll
            for (int ni = 0; ni < NF; ni++) {
                int n = wn * WNT + ni * 8 + rq;
                bf[ni][0] = Bs[n * LDS + c];
                bf[ni][1] = Bs[n * LDS + c + 4];
            }
#pragma unroll
            for (int mi = 0; mi < MF; mi++)
#pragma unroll
                for (int ni = 0; ni < NF; ni++)
                    mma_tf32(acc[mi][ni], af[mi], bf[ni]);
        }
        __syncthreads();
    }

    // ---- epilogue ----
#pragma unroll
    for (int mi = 0; mi < MF; mi++) {
        int r_lo = row0 + wm * WMT + mi * 16 + (lane >> 2);
#pragma unroll
        for (int ni = 0; ni < NF; ni++) {
            int gc = col0 + wn * WNT + ni * 8 + 2 * (lane & 3);
            if (r_lo < N)
                *reinterpret_cast<float2*>(C + (size_t)r_lo * M + gc) =
                    make_float2(acc[mi][ni][0], acc[mi][ni][1]);
            if (r_lo + 8 < N)
                *reinterpret_cast<float2*>(C + (size_t)(r_lo + 8) * M + gc) =
                    make_float2(acc[mi][ni][2], acc[mi][ni][3]);
        }
    }
}

// ---------------------------------------------------------------------------
// L1: out[n][0:128] = relu(a[n][0:3] @ W1 + b1). 32 threads/node, 4 cols each.
// ---------------------------------------------------------------------------
__global__ void l1_kernel(const float* __restrict__ a, const float* __restrict__ W,
                          const float* __restrict__ bias, float* __restrict__ out, int N) {
    int tid = blockIdx.x * blockDim.x + threadIdx.x;
    int node = tid >> 5;
    int c4 = (tid & 31) * 4;
    if (node >= N) return;
    float a0 = a[(size_t)node * 3 + 0];
    float a1 = a[(size_t)node * 3 + 1];
    float a2 = a[(size_t)node * 3 + 2];
    float4 w0 = *reinterpret_cast<const float4*>(W + 0 * 128 + c4);
    float4 w1 = *reinterpret_cast<const float4*>(W + 1 * 128 + c4);
    float4 w2 = *reinterpret_cast<const float4*>(W + 2 * 128 + c4);
    float4 b  = *reinterpret_cast<const float4*>(bias + c4);
    float4 v;
    v.x = fmaxf(a0 * w0.x + a1 * w1.x + a2 * w2.x + b.x, 0.f);
    v.y = fmaxf(a0 * w0.y + a1 * w1.y + a2 * w2.y + b.y, 0.f);
    v.z = fmaxf(a0 * w0.z + a1 * w1.z + a2 * w2.z + b.z, 0.f);
    v.w = fmaxf(a0 * w0.w + a1 * w1.w + a2 * w2.w + b.w, 0.f);
    *reinterpret_cast<float4*>(out + (size_t)node * 128 + c4) = v;
}

// M=1 GEMV (layer 5): warp per row, shuffle reduce.
__global__ void gemv_kernel(const float* __restrict__ A, const float* __restrict__ w,
                            float* __restrict__ out, int N, int K) {
    int warp = (blockIdx.x * blockDim.x + threadIdx.x) / 32;
    int lane = threadIdx.x % 32;
    if (warp >= N) return;
    float acc = 0.0f;
    for (int k = lane; k < K; k += 32) acc += A[(size_t)warp * K + k] * w[k];
#pragma unroll
    for (int off = 16; off > 0; off >>= 1) acc += __shfl_down_sync(0xffffffffu, acc, off);
    if (lane == 0) out[warp] = acc;
}

// ---------------------------------------------------------------------------
// Launch
// ---------------------------------------------------------------------------
extern "C" void kernel_launch(void* const* d_in, const int* in_sizes, int n_in,
                              void* d_out, int out_size) {
    const float* x  = (const float*)d_in[0];
    const int*   ei = (const int*)d_in[1];
    const float* W1 = (const float*)d_in[2];
    const float* b1 = (const float*)d_in[3];
    const float* W2 = (const float*)d_in[4];
    const float* b2 = (const float*)d_in[5];
    const float* W3 = (const float*)d_in[6];
    const float* b3 = (const float*)d_in[7];
    const float* W4 = (const float*)d_in[8];
    const float* b4 = (const float*)d_in[9];
    const float* W5 = (const float*)d_in[10];
    const float* b5 = (const float*)d_in[11];

    int N = in_sizes[0] / 3;
    int E = in_sizes[1] / 2;
    const int* row = ei;       // sources (gather index)
    const int* col = ei + E;   // targets (aggregation index)

    float *bufA, *bufB, *dinv, *cw;
    int *deg, *cnt, *rowptr, *blocksums, *csrc;
    cudaGetSymbolAddress((void**)&bufA, g_bufA);
    cudaGetSymbolAddress((void**)&bufB, g_bufB);
    cudaGetSymbolAddress((void**)&deg, g_deg);
    cudaGetSymbolAddress((void**)&cnt, g_cnt);
    cudaGetSymbolAddress((void**)&rowptr, g_rowptr);
    cudaGetSymbolAddress((void**)&blocksums, g_blocksums);
    cudaGetSymbolAddress((void**)&dinv, g_dinv);
    cudaGetSymbolAddress((void**)&csrc, g_csrc);
    cudaGetSymbolAddress((void**)&cw, g_cw);

    const int T = 256;
    auto cdiv = [](long long a, long long b) { return (int)((a + b - 1) / b); };
    int nb = cdiv(N, 1024);

    // ---- CSR build ----
    cudaMemsetAsync(deg, 0, (size_t)N * sizeof(int));
    cudaMemsetAsync(cnt, 0, (size_t)N * sizeof(int));
    count_deg_kernel<<<cdiv(E, T), T>>>(col, deg, E);
    dinv_kernel<<<cdiv(N, T), T>>>(deg, dinv, N);
    scan_block_kernel<<<nb, 1024>>>(deg, rowptr, blocksums, N);
    scan_sums_kernel<<<1, 128>>>(blocksums, nb);
    scan_add_kernel<<<cdiv(N, T), T>>>(rowptr, blocksums, N, E);
    csr_fill_kernel<<<cdiv(E, T), T>>>(row, col, dinv, rowptr, cnt, csrc, cw, E);

    // ---- L1: agg(x) [D=3], then 3->128 (+b1, relu) ----
    agg_csr3_kernel<<<cdiv(N, T), T>>>(x, rowptr, csrc, cw, dinv, bufA, N);
    l1_kernel<<<cdiv((long long)N * 32, T), T>>>(bufA, W1, b1, bufB, N);

    // ---- L2: TF32 GEMM 128->128, then agg (+b2, relu) ----
    {
        dim3 g(1, cdiv(N, 128));
        gemm_tf32_kernel<128, 2, 4><<<g, T>>>(bufB, W2, bufA, N, 128, 128);
    }
    agg_csr_kernel<128, true, true><<<cdiv((long long)N * 32, T), T>>>(
        bufA, rowptr, csrc, cw, dinv, b2, bufB, N);

    // ---- L3: TF32 GEMM 128->64, then agg (+b3, relu) ----
    {
        dim3 g(1, cdiv(N, 128));
        gemm_tf32_kernel<64, 4, 2><<<g, T>>>(bufB, W3, bufA, N, 128, 64);
    }
    agg_csr_kernel<64, true, true><<<cdiv((long long)N * 16, T), T>>>(
        bufA, rowptr, csrc, cw, dinv, b3, bufB, N);

    // ---- L4: TF32 GEMM 64->64, then agg (+b4, relu) ----
    {
        dim3 g(1, cdiv(N, 128));
        gemm_tf32_kernel<64, 4, 2><<<g, T>>>(bufB, W4, bufA, N, 64, 64);
    }
    agg_csr_kernel<64, true, true><<<cdiv((long long)N * 16, T), T>>>(
        bufA, rowptr, csrc, cw, dinv, b4, bufB, N);

    // ---- L5: GEMV 64->1, then agg (+b5) into d_out ----
    gemv_kernel<<<cdiv((long long)N * 32, T), T>>>(bufB, W5, bufA, N, 64);
    agg_csr1_kernel<<<cdiv(N, T), T>>>(bufA, rowptr, csrc, cw, dinv, b5, (float*)d_out, N);
}